// round 1
// baseline (speedup 1.0000x reference)
#include <cuda_runtime.h>
#include <math.h>

// ---------------- problem constants ----------------
#define BB    2
#define LL    2048
#define DD    256
#define DIN   512
#define NH    8
#define HD    64
#define NST   64
#define CDIM  640
#define NPROJ 1160
#define ROWS  (BB*LL)      // 4096
#define NC    32           // chunks per sequence
#define QC    64           // chunk length

// ---------------- scratch (device globals; no runtime alloc) ----------------
__device__ float g_xln   [ROWS*DD];
__device__ float g_zx    [ROWS*NPROJ];
__device__ float g_xact  [ROWS*DIN];
__device__ float g_Bm    [ROWS*NST];
__device__ float g_Cm    [ROWS*NST];
__device__ float g_dt    [ROWS*NH];
__device__ float g_dlog  [ROWS*NH];
__device__ float g_chunkS[BB*NH*NC*HD*NST];   // per-chunk partial state [p][n]
__device__ float g_lend  [BB*NH*NC];
__device__ float g_SinT  [BB*NH*NC*HD*NST];   // state entering chunk, TRANSPOSED [n][p]
__device__ float g_y     [ROWS*DIN];

// ---------------- K1: LayerNorm + residual copy ----------------
__global__ void __launch_bounds__(256) k_ln(const float* __restrict__ hid,
                                            const float* __restrict__ w,
                                            const float* __restrict__ b,
                                            float* __restrict__ resid) {
    int row = blockIdx.x, t = threadIdx.x;
    float v = hid[row*DD + t];
    float s = v, q = v*v;
    #pragma unroll
    for (int o = 16; o; o >>= 1) {
        s += __shfl_xor_sync(0xffffffffu, s, o);
        q += __shfl_xor_sync(0xffffffffu, q, o);
    }
    __shared__ float r1[8], r2[8];
    if ((t & 31) == 0) { r1[t>>5] = s; r2[t>>5] = q; }
    __syncthreads();
    __shared__ float smu, srs;
    if (t == 0) {
        float S = 0.f, Qs = 0.f;
        for (int i = 0; i < 8; i++) { S += r1[i]; Qs += r2[i]; }
        float mu = S / 256.f;
        smu = mu;
        srs = rsqrtf(Qs/256.f - mu*mu + 1e-5f);
    }
    __syncthreads();
    g_xln[row*DD + t] = (v - smu) * srs * w[t] + b[t];
    resid[row*DD + t] = v;
}

// ---------------- generic fp32 SGEMM body: C[M=4096,Nn] = A[4096,K] @ Bw[K,Nn] ----------------
__device__ __forceinline__ void gemm_body(const float* __restrict__ A,
                                          const float* __restrict__ Bw,
                                          float* __restrict__ C, int Nn, int K) {
    __shared__ float As[16][132];
    __shared__ float Bs[16][64];
    const int bm = blockIdx.y * 128;
    const int bn = blockIdx.x * 64;
    const int tid = threadIdx.x;
    const int tx = tid & 15, ty = tid >> 4;
    float acc[8][4];
    #pragma unroll
    for (int i = 0; i < 8; i++)
        #pragma unroll
        for (int j = 0; j < 4; j++) acc[i][j] = 0.f;

    for (int k0 = 0; k0 < K; k0 += 16) {
        #pragma unroll
        for (int u = 0; u < 8; ++u) {
            int i = tid + u*256;
            int m = i >> 4, k = i & 15;
            As[k][m] = A[(bm+m)*K + k0 + k];
        }
        #pragma unroll
        for (int u = 0; u < 4; ++u) {
            int i = tid + u*256;
            int k = i >> 6, n = i & 63;
            int col = bn + n;
            Bs[k][n] = (col < Nn) ? Bw[(k0+k)*Nn + col] : 0.f;
        }
        __syncthreads();
        #pragma unroll
        for (int k = 0; k < 16; ++k) {
            float a[8], bv[4];
            #pragma unroll
            for (int i = 0; i < 8; i++) a[i] = As[k][ty*8 + i];
            #pragma unroll
            for (int j = 0; j < 4; j++) bv[j] = Bs[k][tx*4 + j];
            #pragma unroll
            for (int i = 0; i < 8; i++)
                #pragma unroll
                for (int j = 0; j < 4; j++) acc[i][j] += a[i]*bv[j];
        }
        __syncthreads();
    }
    #pragma unroll
    for (int i = 0; i < 8; i++) {
        int row = bm + ty*8 + i;
        #pragma unroll
        for (int j = 0; j < 4; j++) {
            int col = bn + tx*4 + j;
            if (col < Nn) C[row*Nn + col] = acc[i][j];
        }
    }
}

__global__ void __launch_bounds__(256) k_gemm_in(const float* __restrict__ Win) {
    gemm_body(g_xln, Win, g_zx, NPROJ, DD);
}
__global__ void __launch_bounds__(256) k_gemm_out(const float* __restrict__ Wout,
                                                  float* __restrict__ out) {
    gemm_body(g_y, Wout, out, DD, DIN);
}

// ---------------- K3: causal depthwise conv + SiLU, and softplus(dt) ----------------
__global__ void __launch_bounds__(256) k_conv(const float* __restrict__ cw,
                                              const float* __restrict__ cb,
                                              const float* __restrict__ dtb,
                                              const float* __restrict__ Alog) {
    int idx = blockIdx.x * 256 + threadIdx.x;
    if (idx >= ROWS * 648) return;
    int c = idx % 648;
    int row = idx / 648;
    int b = row / LL, l = row % LL;
    if (c < CDIM) {
        float acc = cb[c];
        #pragma unroll
        for (int k = 0; k < 4; k++) {
            int ls = l + k - 3;
            if (ls >= 0) acc += cw[c*4 + k] * g_zx[(b*LL + ls)*NPROJ + 512 + c];
        }
        float sv = acc / (1.f + expf(-acc));
        if (c < DIN)        g_xact[row*DIN + c] = sv;
        else if (c < 576)   g_Bm[row*NST + (c - 512)] = sv;
        else                g_Cm[row*NST + (c - 576)] = sv;
    } else {
        int h = c - CDIM;
        float raw = g_zx[row*NPROJ + 1152 + h] + dtb[h];
        float dt = (raw > 20.f) ? raw : log1pf(expf(raw));
        g_dt[row*NH + h]   = dt;
        g_dlog[row*NH + h] = -dt * expf(Alog[h]);   // dt * A
    }
}

// ---------------- K4: per-chunk partial state S_c[p,n] = sum_j exp(Lend-L_j)*dt_j*x_j[p]*B_j[n] ----------------
__global__ void __launch_bounds__(256) k_cstate() {
    __shared__ float sx[64][65];
    __shared__ float sb[64][65];
    __shared__ float sl[64], scoef[64];
    int bid = blockIdx.x;                 // (b,h,c) : 512 blocks
    int c = bid & 31, h = (bid >> 5) & 7, b = bid >> 8;
    int tid = threadIdx.x;
    int t0 = b*LL + c*QC;

    if (tid < 64) sl[tid] = g_dlog[(t0 + tid)*NH + h];
    __syncthreads();
    if (tid == 0) { float a = 0.f; for (int j = 0; j < 64; j++) { a += sl[j]; sl[j] = a; } }
    __syncthreads();
    float lend = sl[63];
    if (tid < 64) scoef[tid] = expf(lend - sl[tid]) * g_dt[(t0 + tid)*NH + h];
    for (int i = tid; i < 4096; i += 256) {
        int j = i >> 6, p = i & 63;
        sx[j][p] = g_xact[(t0 + j)*DIN + h*HD + p];
        sb[j][p] = g_Bm[(t0 + j)*NST + p];
    }
    __syncthreads();
    if (tid == 0) g_lend[bid] = lend;

    int tx = tid & 15, ty = tid >> 4;
    int p0 = ty*4, n0 = tx*4;
    float acc[4][4];
    #pragma unroll
    for (int i = 0; i < 4; i++)
        #pragma unroll
        for (int j = 0; j < 4; j++) acc[i][j] = 0.f;
    for (int j = 0; j < 64; ++j) {
        float cf = scoef[j];
        float a[4], bb[4];
        #pragma unroll
        for (int i = 0; i < 4; i++) { a[i] = cf * sx[j][p0+i]; bb[i] = sb[j][n0+i]; }
        #pragma unroll
        for (int i = 0; i < 4; i++)
            #pragma unroll
            for (int n = 0; n < 4; n++) acc[i][n] += a[i]*bb[n];
    }
    float* op = g_chunkS + (size_t)bid*4096;
    #pragma unroll
    for (int i = 0; i < 4; i++)
        #pragma unroll
        for (int n = 0; n < 4; n++) op[(p0+i)*64 + n0+n] = acc[i][n];
}

// ---------------- K5: sequential inter-chunk recurrence (16 chains x 32 steps) ----------------
__global__ void __launch_bounds__(256) k_seq() {
    int bh = blockIdx.x, tid = threadIdx.x;
    float s[16];
    #pragma unroll
    for (int k = 0; k < 16; k++) s[k] = 0.f;
    for (int c = 0; c < NC; c++) {
        size_t base = (size_t)(bh*NC + c)*4096;
        float a = expf(g_lend[bh*NC + c]);
        #pragma unroll
        for (int k = 0; k < 16; k++) {
            int e = tid + k*256;                    // e = p*64 + n
            g_SinT[base + (size_t)((e & 63)*64 + (e >> 6))] = s[k];   // store [n][p]
            s[k] = s[k]*a + g_chunkS[base + e];
        }
    }
}

// ---------------- K6: intra-chunk Y + inter-chunk contribution + D*x ----------------
__global__ void __launch_bounds__(256) k_y(const float* __restrict__ Dp) {
    __shared__ float bufA[64*65];   // B (staged) -> then masked M matrix
    __shared__ float bufB[64*65];   // C (staged) -> then X
    __shared__ float sl[64], sdt[64];
    int bid = blockIdx.x;
    int c = bid & 31, h = (bid >> 5) & 7, b = bid >> 8;
    int tid = threadIdx.x;
    int t0 = b*LL + c*QC;

    for (int i = tid; i < 4096; i += 256) {
        int r = i >> 6, q = i & 63;
        bufA[r*65 + q] = g_Bm[(t0 + r)*NST + q];
        bufB[r*65 + q] = g_Cm[(t0 + r)*NST + q];
    }
    if (tid < 64) { sl[tid] = g_dlog[(t0 + tid)*NH + h]; sdt[tid] = g_dt[(t0 + tid)*NH + h]; }
    __syncthreads();
    if (tid == 0) { float a = 0.f; for (int j = 0; j < 64; j++) { a += sl[j]; sl[j] = a; } }
    __syncthreads();

    int tx = tid & 15, ty = tid >> 4;
    int ti = ty*4, j0 = tx*4;                 // j0 doubles as p0 later
    float Lts[4], Ljs[4], dts[4], expL[4];
    #pragma unroll
    for (int i = 0; i < 4; i++) {
        Lts[i] = sl[ti + i];  Ljs[i] = sl[j0 + i];  dts[i] = sdt[j0 + i];
        expL[i] = expf(Lts[i]);
    }

    // GEMM1: G[t,j] = sum_n C[t][n] * B[j][n]
    float g[4][4];
    #pragma unroll
    for (int i = 0; i < 4; i++)
        #pragma unroll
        for (int j = 0; j < 4; j++) g[i][j] = 0.f;
    for (int n = 0; n < 64; ++n) {
        float cv[4], bv[4];
        #pragma unroll
        for (int i = 0; i < 4; i++) { cv[i] = bufB[(ti+i)*65 + n]; bv[i] = bufA[(j0+i)*65 + n]; }
        #pragma unroll
        for (int i = 0; i < 4; i++)
            #pragma unroll
            for (int j = 0; j < 4; j++) g[i][j] += cv[i]*bv[j];
    }

    // term2: Y[t,p] = exp(L_t) * sum_n C[t][n] * S_in[p][n]   (SinT stored [n][p])
    const float* sinp = g_SinT + (size_t)bid*4096;
    float Y[4][4];
    #pragma unroll
    for (int i = 0; i < 4; i++)
        #pragma unroll
        for (int j = 0; j < 4; j++) Y[i][j] = 0.f;
    for (int n = 0; n < 64; ++n) {
        float4 sv4 = *(const float4*)(sinp + n*64 + j0);
        float sv[4] = {sv4.x, sv4.y, sv4.z, sv4.w};
        float cvv[4];
        #pragma unroll
        for (int i = 0; i < 4; i++) cvv[i] = expL[i] * bufB[(ti+i)*65 + n];
        #pragma unroll
        for (int i = 0; i < 4; i++)
            #pragma unroll
            for (int j = 0; j < 4; j++) Y[i][j] += cvv[i]*sv[j];
    }
    __syncthreads();   // all reads of bufA(B)/bufB(C) done

    // write masked M into bufA; stage X into bufB
    #pragma unroll
    for (int i = 0; i < 4; i++)
        #pragma unroll
        for (int j = 0; j < 4; j++) {
            int tt = ti + i, jj = j0 + j;
            bufA[tt*65 + jj] = (tt >= jj) ? expf(Lts[i] - Ljs[j]) * dts[j] * g[i][j] : 0.f;
        }
    for (int i = tid; i < 4096; i += 256) {
        int r = i >> 6, q = i & 63;
        bufB[r*65 + q] = g_xact[(t0 + r)*DIN + h*HD + q];
    }
    __syncthreads();

    // GEMM2: Y[t,p] += sum_j M[t,j] * X[j,p]
    for (int j = 0; j < 64; ++j) {
        float mv[4], xv[4];
        #pragma unroll
        for (int i = 0; i < 4; i++) { mv[i] = bufA[(ti+i)*65 + j]; xv[i] = bufB[j*65 + j0 + i]; }
        #pragma unroll
        for (int i = 0; i < 4; i++)
            #pragma unroll
            for (int jj = 0; jj < 4; jj++) Y[i][jj] += mv[i]*xv[jj];
    }

    float Dh = Dp[h];
    #pragma unroll
    for (int i = 0; i < 4; i++)
        #pragma unroll
        for (int j = 0; j < 4; j++) {
            float yv = Y[i][j] + Dh * bufB[(ti+i)*65 + j0 + j];
            g_y[(t0 + ti + i)*DIN + h*HD + j0 + j] = yv;
        }
}

// ---------------- K7: gating (y * silu(z)) + RMSNorm, in place on g_y ----------------
__global__ void __launch_bounds__(256) k_gate(const float* __restrict__ rmsw) {
    int row = blockIdx.x, t = threadIdx.x;
    float gv[2]; float ss = 0.f;
    #pragma unroll
    for (int k = 0; k < 2; k++) {
        int i = t + k*256;
        float z = g_zx[row*NPROJ + i];
        float v = g_y[row*DIN + i] * (z / (1.f + expf(-z)));
        gv[k] = v; ss += v*v;
    }
    #pragma unroll
    for (int o = 16; o; o >>= 1) ss += __shfl_xor_sync(0xffffffffu, ss, o);
    __shared__ float red[8];
    if ((t & 31) == 0) red[t>>5] = ss;
    __syncthreads();
    __shared__ float scale;
    if (t == 0) {
        float tot = 0.f;
        for (int i = 0; i < 8; i++) tot += red[i];
        scale = rsqrtf(tot/512.f + 1e-5f);
    }
    __syncthreads();
    #pragma unroll
    for (int k = 0; k < 2; k++) {
        int i = t + k*256;
        g_y[row*DIN + i] = gv[k] * scale * rmsw[i];
    }
}

// ---------------- launch ----------------
extern "C" void kernel_launch(void* const* d_in, const int* in_sizes, int n_in,
                              void* d_out, int out_size) {
    const float* hid   = (const float*)d_in[0];
    const float* normw = (const float*)d_in[1];
    const float* normb = (const float*)d_in[2];
    const float* Win   = (const float*)d_in[3];
    const float* convw = (const float*)d_in[4];
    const float* convb = (const float*)d_in[5];
    const float* dtb   = (const float*)d_in[6];
    const float* Alog  = (const float*)d_in[7];
    const float* Dp    = (const float*)d_in[8];
    const float* rmsw  = (const float*)d_in[9];
    const float* Wout  = (const float*)d_in[10];
    float* out   = (float*)d_out;
    float* resid = out + out_size/2;

    k_ln      <<<ROWS, 256>>>(hid, normw, normb, resid);
    k_gemm_in <<<dim3((NPROJ + 63)/64, ROWS/128), 256>>>(Win);
    k_conv    <<<(ROWS*648 + 255)/256, 256>>>(convw, convb, dtb, Alog);
    k_cstate  <<<BB*NH*NC, 256>>>();
    k_seq     <<<BB*NH, 256>>>();
    k_y       <<<BB*NH*NC, 256>>>(Dp);
    k_gate    <<<ROWS, 256>>>(rmsw);
    k_gemm_out<<<dim3(DD/64, ROWS/128), 256>>>(Wout, out);
}

// round 3
// speedup vs baseline: 2.8750x; 2.8750x over previous
#include <cuda_runtime.h>
#include <cuda_bf16.h>
#include <math.h>
#include <stdint.h>

// ---------------- problem constants ----------------
#define BB    2
#define LL    2048
#define DD    256
#define DIN   512
#define NH    8
#define HD    64
#define NST   64
#define CDIM  640
#define NPROJ 1160
#define ROWS  (BB*LL)      // 4096
#define NC    32           // chunks per sequence
#define QC    64           // chunk length

// ---------------- scratch (device globals; no runtime alloc) ----------------
__device__ __align__(16) float g_xln   [ROWS*DD];
__device__ __align__(16) float g_zx    [ROWS*NPROJ];
__device__ __align__(16) float g_xact  [ROWS*DIN];
__device__ __align__(16) float g_Bm    [ROWS*NST];
__device__ __align__(16) float g_Cm    [ROWS*NST];
__device__ __align__(16) float g_dt    [ROWS*NH];
__device__ __align__(16) float g_dlog  [ROWS*NH];
__device__ __align__(16) float g_chunkS[BB*NH*NC*HD*NST];
__device__ __align__(16) float g_lend  [BB*NH*NC];
__device__ __align__(16) float g_SinT  [BB*NH*NC*HD*NST];
__device__ __align__(16) float g_y     [ROWS*DIN];

// ================= warp-level bf16 MMA helpers =================
__device__ __forceinline__ void mma16816(float* c, const uint32_t* a, const uint32_t* b) {
    asm volatile(
        "mma.sync.aligned.m16n8k16.row.col.f32.bf16.bf16.f32 "
        "{%0,%1,%2,%3}, {%4,%5,%6,%7}, {%8,%9}, {%0,%1,%2,%3};"
        : "+f"(c[0]), "+f"(c[1]), "+f"(c[2]), "+f"(c[3])
        : "r"(a[0]), "r"(a[1]), "r"(a[2]), "r"(a[3]), "r"(b[0]), "r"(b[1]));
}
__device__ __forceinline__ uint32_t pk(float a, float b) {
    __nv_bfloat162 t = __floats2bfloat162_rn(a, b);
    return *reinterpret_cast<uint32_t*>(&t);
}

#define SSTR 72                       // smem row stride in bf16 elems
#define OFF_AH 0
#define OFF_AL (128*SSTR)
#define OFF_BH (2*128*SSTR)
#define OFF_BL (2*128*SSTR + 64*SSTR)
#define TG_DSMEM ((2*128*SSTR + 2*64*SSTR) * 2)   // 55296 bytes

// ============ tensor-core GEMM: C[4096,Nn] = A[4096,K] @ W[K,Nn], bf16x3 ============
__device__ __forceinline__ void tgemm_body(const float* __restrict__ A,
                                           const float* __restrict__ W,
                                           float* __restrict__ C, int Nn, int K) {
    extern __shared__ __nv_bfloat16 sm[];
    __nv_bfloat16* sAh = sm + OFF_AH;
    __nv_bfloat16* sAl = sm + OFF_AL;
    __nv_bfloat16* sBh = sm + OFF_BH;
    __nv_bfloat16* sBl = sm + OFF_BL;

    const int bm = blockIdx.y * 128;
    const int bn = blockIdx.x * 64;
    const int tid = threadIdx.x;
    const int wid = tid >> 5, lane = tid & 31;
    const int wm = (wid >> 1) * 32;       // warp m offset in tile
    const int wn = (wid & 1) * 32;        // warp n offset in tile

    float acc[2][4][4];
    #pragma unroll
    for (int i = 0; i < 2; i++)
        #pragma unroll
        for (int j = 0; j < 4; j++)
            #pragma unroll
            for (int k = 0; k < 4; k++) acc[i][j][k] = 0.f;

    for (int k0 = 0; k0 < K; k0 += 64) {
        // ---- stage A panel [128 x 64] hi/lo ----
        #pragma unroll
        for (int u = 0; u < 8; ++u) {
            int i = tid + u * 256;            // 0..2047
            int r = i >> 4, c4 = (i & 15) << 2;
            float4 v = *(const float4*)(A + (size_t)(bm + r) * K + k0 + c4);
            float h0 = __bfloat162float(__float2bfloat16(v.x));
            float h1 = __bfloat162float(__float2bfloat16(v.y));
            float h2 = __bfloat162float(__float2bfloat16(v.z));
            float h3 = __bfloat162float(__float2bfloat16(v.w));
            int off = r * SSTR + c4;
            *(uint2*)(sAh + off) = make_uint2(pk(h0, h1), pk(h2, h3));
            *(uint2*)(sAl + off) = make_uint2(pk(v.x - h0, v.y - h1), pk(v.z - h2, v.w - h3));
        }
        // ---- stage B panel: B[n][k] = W[k0+k][bn+n], [64 x 64] hi/lo ----
        #pragma unroll
        for (int u = 0; u < 4; ++u) {
            int i = tid + u * 256;            // 0..1023
            int n = i & 63, g = i >> 6;       // g = k-group 0..15
            int col = bn + n;
            float v0 = 0.f, v1 = 0.f, v2 = 0.f, v3 = 0.f;
            if (col < Nn) {
                const float* wp = W + (size_t)(k0 + (g << 2)) * Nn + col;
                v0 = wp[0]; v1 = wp[Nn]; v2 = wp[2 * Nn]; v3 = wp[3 * Nn];
            }
            float h0 = __bfloat162float(__float2bfloat16(v0));
            float h1 = __bfloat162float(__float2bfloat16(v1));
            float h2 = __bfloat162float(__float2bfloat16(v2));
            float h3 = __bfloat162float(__float2bfloat16(v3));
            int off = n * SSTR + (g << 2);
            *(uint2*)(sBh + off) = make_uint2(pk(h0, h1), pk(h2, h3));
            *(uint2*)(sBl + off) = make_uint2(pk(v0 - h0, v1 - h1), pk(v2 - h2, v3 - h3));
        }
        __syncthreads();

        #pragma unroll
        for (int ks = 0; ks < 4; ++ks) {
            const int c = ks * 16 + (lane & 3) * 2;      // k column (bf16 idx)
            const int ra = wm + (lane >> 2);
            uint32_t ah[2][4], al[2][4], bh[4][2], bl[4][2];
            #pragma unroll
            for (int mf = 0; mf < 2; ++mf) {
                int r0 = (ra + mf * 16) * SSTR;
                int r8 = r0 + 8 * SSTR;
                ah[mf][0] = *(const uint32_t*)(sAh + r0 + c);
                ah[mf][1] = *(const uint32_t*)(sAh + r8 + c);
                ah[mf][2] = *(const uint32_t*)(sAh + r0 + c + 8);
                ah[mf][3] = *(const uint32_t*)(sAh + r8 + c + 8);
                al[mf][0] = *(const uint32_t*)(sAl + r0 + c);
                al[mf][1] = *(const uint32_t*)(sAl + r8 + c);
                al[mf][2] = *(const uint32_t*)(sAl + r0 + c + 8);
                al[mf][3] = *(const uint32_t*)(sAl + r8 + c + 8);
            }
            #pragma unroll
            for (int nf = 0; nf < 4; ++nf) {
                int nr = (wn + nf * 8 + (lane >> 2)) * SSTR;
                bh[nf][0] = *(const uint32_t*)(sBh + nr + c);
                bh[nf][1] = *(const uint32_t*)(sBh + nr + c + 8);
                bl[nf][0] = *(const uint32_t*)(sBl + nr + c);
                bl[nf][1] = *(const uint32_t*)(sBl + nr + c + 8);
            }
            #pragma unroll
            for (int mf = 0; mf < 2; ++mf)
                #pragma unroll
                for (int nf = 0; nf < 4; ++nf) {
                    mma16816(acc[mf][nf], ah[mf], bh[nf]);
                    mma16816(acc[mf][nf], ah[mf], bl[nf]);
                    mma16816(acc[mf][nf], al[mf], bh[nf]);
                }
        }
        __syncthreads();
    }

    // ---- store C ----
    #pragma unroll
    for (int mf = 0; mf < 2; ++mf) {
        int row0 = bm + wm + mf * 16 + (lane >> 2);
        #pragma unroll
        for (int nf = 0; nf < 4; ++nf) {
            int col = bn + wn + nf * 8 + (lane & 3) * 2;
            if (col < Nn) {
                float* p0 = C + (size_t)row0 * Nn + col;
                float* p1 = C + (size_t)(row0 + 8) * Nn + col;
                p0[0] = acc[mf][nf][0]; p0[1] = acc[mf][nf][1];
                p1[0] = acc[mf][nf][2]; p1[1] = acc[mf][nf][3];
            }
        }
    }
}

__global__ void __launch_bounds__(256) k_tgemm_in(const float* __restrict__ Win) {
    tgemm_body(g_xln, Win, g_zx, NPROJ, DD);
}
__global__ void __launch_bounds__(256) k_tgemm_out(const float* __restrict__ Wout,
                                                   float* __restrict__ out) {
    tgemm_body(g_y, Wout, out, DD, DIN);
}

// ---------------- K1: LayerNorm + residual copy ----------------
__global__ void __launch_bounds__(256) k_ln(const float* __restrict__ hid,
                                            const float* __restrict__ w,
                                            const float* __restrict__ b,
                                            float* __restrict__ resid) {
    int row = blockIdx.x, t = threadIdx.x;
    float v = hid[row*DD + t];
    float s = v, q = v*v;
    #pragma unroll
    for (int o = 16; o; o >>= 1) {
        s += __shfl_xor_sync(0xffffffffu, s, o);
        q += __shfl_xor_sync(0xffffffffu, q, o);
    }
    __shared__ float r1[8], r2[8];
    if ((t & 31) == 0) { r1[t>>5] = s; r2[t>>5] = q; }
    __syncthreads();
    __shared__ float smu, srs;
    if (t == 0) {
        float S = 0.f, Qs = 0.f;
        for (int i = 0; i < 8; i++) { S += r1[i]; Qs += r2[i]; }
        float mu = S / 256.f;
        smu = mu;
        srs = rsqrtf(Qs/256.f - mu*mu + 1e-5f);
    }
    __syncthreads();
    g_xln[row*DD + t] = (v - smu) * srs * w[t] + b[t];
    resid[row*DD + t] = v;
}

// ---------------- K3: causal depthwise conv + SiLU, and softplus(dt) ----------------
__global__ void __launch_bounds__(256) k_conv(const float* __restrict__ cw,
                                              const float* __restrict__ cb,
                                              const float* __restrict__ dtb,
                                              const float* __restrict__ Alog) {
    int idx = blockIdx.x * 256 + threadIdx.x;
    if (idx >= ROWS * 648) return;
    int c = idx % 648;
    int row = idx / 648;
    int b = row / LL, l = row % LL;
    if (c < CDIM) {
        float acc = cb[c];
        #pragma unroll
        for (int k = 0; k < 4; k++) {
            int ls = l + k - 3;
            if (ls >= 0) acc += cw[c*4 + k] * g_zx[(b*LL + ls)*NPROJ + 512 + c];
        }
        float sv = acc / (1.f + expf(-acc));
        if (c < DIN)        g_xact[row*DIN + c] = sv;
        else if (c < 576)   g_Bm[row*NST + (c - 512)] = sv;
        else                g_Cm[row*NST + (c - 576)] = sv;
    } else {
        int h = c - CDIM;
        float raw = g_zx[row*NPROJ + 1152 + h] + dtb[h];
        float dt = (raw > 20.f) ? raw : log1pf(expf(raw));
        g_dt[row*NH + h]   = dt;
        g_dlog[row*NH + h] = -dt * expf(Alog[h]);
    }
}

// ---------------- K4: per-chunk partial state ----------------
__global__ void __launch_bounds__(256) k_cstate() {
    __shared__ float sx[64][65];
    __shared__ float sb[64][65];
    __shared__ float sl[64], scoef[64];
    int bid = blockIdx.x;
    int c = bid & 31, h = (bid >> 5) & 7, b = bid >> 8;
    int tid = threadIdx.x;
    int t0 = b*LL + c*QC;

    if (tid < 64) sl[tid] = g_dlog[(t0 + tid)*NH + h];
    __syncthreads();
    if (tid == 0) { float a = 0.f; for (int j = 0; j < 64; j++) { a += sl[j]; sl[j] = a; } }
    __syncthreads();
    float lend = sl[63];
    if (tid < 64) scoef[tid] = expf(lend - sl[tid]) * g_dt[(t0 + tid)*NH + h];
    for (int i = tid; i < 4096; i += 256) {
        int j = i >> 6, p = i & 63;
        sx[j][p] = g_xact[(t0 + j)*DIN + h*HD + p];
        sb[j][p] = g_Bm[(t0 + j)*NST + p];
    }
    __syncthreads();
    if (tid == 0) g_lend[bid] = lend;

    int tx = tid & 15, ty = tid >> 4;
    int p0 = ty*4, n0 = tx*4;
    float acc[4][4];
    #pragma unroll
    for (int i = 0; i < 4; i++)
        #pragma unroll
        for (int j = 0; j < 4; j++) acc[i][j] = 0.f;
    for (int j = 0; j < 64; ++j) {
        float cf = scoef[j];
        float a[4], bb[4];
        #pragma unroll
        for (int i = 0; i < 4; i++) { a[i] = cf * sx[j][p0+i]; bb[i] = sb[j][n0+i]; }
        #pragma unroll
        for (int i = 0; i < 4; i++)
            #pragma unroll
            for (int n = 0; n < 4; n++) acc[i][n] += a[i]*bb[n];
    }
    float* op = g_chunkS + (size_t)bid*4096;
    #pragma unroll
    for (int i = 0; i < 4; i++)
        #pragma unroll
        for (int n = 0; n < 4; n++) op[(p0+i)*64 + n0+n] = acc[i][n];
}

// ---------------- K5: inter-chunk recurrence ----------------
__global__ void __launch_bounds__(256) k_seq() {
    int bh = blockIdx.x >> 4, part = blockIdx.x & 15, tid = threadIdx.x;
    int e = part * 256 + tid;                     // e = p*64 + n
    int tr = (e & 63) * 64 + (e >> 6);            // transposed [n][p]
    float s = 0.f;
    for (int c = 0; c < NC; c++) {
        size_t base = (size_t)(bh*NC + c)*4096;
        float a = expf(g_lend[bh*NC + c]);
        g_SinT[base + tr] = s;
        s = s*a + g_chunkS[base + e];
    }
}

// ---------------- K6: intra-chunk Y + inter-chunk contribution + D*x ----------------
__global__ void __launch_bounds__(256) k_y(const float* __restrict__ Dp) {
    __shared__ float bufA[64*65];
    __shared__ float bufB[64*65];
    __shared__ float sl[64], sdt[64];
    int bid = blockIdx.x;
    int c = bid & 31, h = (bid >> 5) & 7, b = bid >> 8;
    int tid = threadIdx.x;
    int t0 = b*LL + c*QC;

    for (int i = tid; i < 4096; i += 256) {
        int r = i >> 6, q = i & 63;
        bufA[r*65 + q] = g_Bm[(t0 + r)*NST + q];
        bufB[r*65 + q] = g_Cm[(t0 + r)*NST + q];
    }
    if (tid < 64) { sl[tid] = g_dlog[(t0 + tid)*NH + h]; sdt[tid] = g_dt[(t0 + tid)*NH + h]; }
    __syncthreads();
    if (tid == 0) { float a = 0.f; for (int j = 0; j < 64; j++) { a += sl[j]; sl[j] = a; } }
    __syncthreads();

    int tx = tid & 15, ty = tid >> 4;
    int ti = ty*4, j0 = tx*4;
    float Lts[4], Ljs[4], dts[4], expL[4];
    #pragma unroll
    for (int i = 0; i < 4; i++) {
        Lts[i] = sl[ti + i];  Ljs[i] = sl[j0 + i];  dts[i] = sdt[j0 + i];
        expL[i] = expf(Lts[i]);
    }

    float g[4][4];
    #pragma unroll
    for (int i = 0; i < 4; i++)
        #pragma unroll
        for (int j = 0; j < 4; j++) g[i][j] = 0.f;
    for (int n = 0; n < 64; ++n) {
        float cv[4], bv[4];
        #pragma unroll
        for (int i = 0; i < 4; i++) { cv[i] = bufB[(ti+i)*65 + n]; bv[i] = bufA[(j0+i)*65 + n]; }
        #pragma unroll
        for (int i = 0; i < 4; i++)
            #pragma unroll
            for (int j = 0; j < 4; j++) g[i][j] += cv[i]*bv[j];
    }

    const float* sinp = g_SinT + (size_t)bid*4096;
    float Y[4][4];
    #pragma unroll
    for (int i = 0; i < 4; i++)
        #pragma unroll
        for (int j = 0; j < 4; j++) Y[i][j] = 0.f;
    for (int n = 0; n < 64; ++n) {
        float4 sv4 = *(const float4*)(sinp + n*64 + j0);
        float sv[4] = {sv4.x, sv4.y, sv4.z, sv4.w};
        float cvv[4];
        #pragma unroll
        for (int i = 0; i < 4; i++) cvv[i] = expL[i] * bufB[(ti+i)*65 + n];
        #pragma unroll
        for (int i = 0; i < 4; i++)
            #pragma unroll
            for (int j = 0; j < 4; j++) Y[i][j] += cvv[i]*sv[j];
    }
    __syncthreads();

    #pragma unroll
    for (int i = 0; i < 4; i++)
        #pragma unroll
        for (int j = 0; j < 4; j++) {
            int tt = ti + i, jj = j0 + j;
            bufA[tt*65 + jj] = (tt >= jj) ? expf(Lts[i] - Ljs[j]) * dts[j] * g[i][j] : 0.f;
        }
    for (int i = tid; i < 4096; i += 256) {
        int r = i >> 6, q = i & 63;
        bufB[r*65 + q] = g_xact[(t0 + r)*DIN + h*HD + q];
    }
    __syncthreads();

    for (int j = 0; j < 64; ++j) {
        float mv[4], xv[4];
        #pragma unroll
        for (int i = 0; i < 4; i++) { mv[i] = bufA[(ti+i)*65 + j]; xv[i] = bufB[j*65 + j0 + i]; }
        #pragma unroll
        for (int i = 0; i < 4; i++)
            #pragma unroll
            for (int jj = 0; jj < 4; jj++) Y[i][jj] += mv[i]*xv[jj];
    }

    float Dh = Dp[h];
    #pragma unroll
    for (int i = 0; i < 4; i++)
        #pragma unroll
        for (int j = 0; j < 4; j++) {
            float yv = Y[i][j] + Dh * bufB[(ti+i)*65 + j0 + j];
            g_y[(t0 + ti + i)*DIN + h*HD + j0 + j] = yv;
        }
}

// ---------------- K7: gating + RMSNorm ----------------
__global__ void __launch_bounds__(256) k_gate(const float* __restrict__ rmsw) {
    int row = blockIdx.x, t = threadIdx.x;
    float gv[2]; float ss = 0.f;
    #pragma unroll
    for (int k = 0; k < 2; k++) {
        int i = t + k*256;
        float z = g_zx[row*NPROJ + i];
        float v = g_y[row*DIN + i] * (z / (1.f + expf(-z)));
        gv[k] = v; ss += v*v;
    }
    #pragma unroll
    for (int o = 16; o; o >>= 1) ss += __shfl_xor_sync(0xffffffffu, ss, o);
    __shared__ float red[8];
    if ((t & 31) == 0) red[t>>5] = ss;
    __syncthreads();
    __shared__ float scale;
    if (t == 0) {
        float tot = 0.f;
        for (int i = 0; i < 8; i++) tot += red[i];
        scale = rsqrtf(tot/512.f + 1e-5f);
    }
    __syncthreads();
    #pragma unroll
    for (int k = 0; k < 2; k++) {
        int i = t + k*256;
        g_y[row*DIN + i] = gv[k] * scale * rmsw[i];
    }
}

// ---------------- launch ----------------
extern "C" void kernel_launch(void* const* d_in, const int* in_sizes, int n_in,
                              void* d_out, int out_size) {
    const float* hid   = (const float*)d_in[0];
    const float* normw = (const float*)d_in[1];
    const float* normb = (const float*)d_in[2];
    const float* Win   = (const float*)d_in[3];
    const float* convw = (const float*)d_in[4];
    const float* convb = (const float*)d_in[5];
    const float* dtb   = (const float*)d_in[6];
    const float* Alog  = (const float*)d_in[7];
    const float* Dp    = (const float*)d_in[8];
    const float* rmsw  = (const float*)d_in[9];
    const float* Wout  = (const float*)d_in[10];
    float* out   = (float*)d_out;
    float* resid = out + out_size/2;

    cudaFuncSetAttribute(k_tgemm_in,  cudaFuncAttributeMaxDynamicSharedMemorySize, TG_DSMEM);
    cudaFuncSetAttribute(k_tgemm_out, cudaFuncAttributeMaxDynamicSharedMemorySize, TG_DSMEM);

    k_ln       <<<ROWS, 256>>>(hid, normw, normb, resid);
    k_tgemm_in <<<dim3((NPROJ + 63)/64, ROWS/128), 256, TG_DSMEM>>>(Win);
    k_conv     <<<(ROWS*648 + 255)/256, 256>>>(convw, convb, dtb, Alog);
    k_cstate   <<<BB*NH*NC, 256>>>();
    k_seq      <<<BB*NH*16, 256>>>();
    k_y        <<<BB*NH*NC, 256>>>(Dp);
    k_gate     <<<ROWS, 256>>>(rmsw);
    k_tgemm_out<<<dim3(DD/64, ROWS/128), 256, TG_DSMEM>>>(Wout, out);
}

// round 4
// speedup vs baseline: 3.1103x; 1.0819x over previous
#include <cuda_runtime.h>
#include <cuda_bf16.h>
#include <math.h>
#include <stdint.h>

// ---------------- problem constants ----------------
#define BB    2
#define LL    2048
#define DD    256
#define DIN   512
#define NH    8
#define HD    64
#define NST   64
#define CDIM  640
#define NPROJ 1160
#define ROWS  (BB*LL)      // 4096
#define NC    32           // chunks per sequence
#define QC    64           // chunk length

// ---------------- scratch (device globals; no runtime alloc) ----------------
__device__ __align__(16) float g_xln   [ROWS*DD];
__device__ __align__(16) float g_zx    [ROWS*NPROJ];
__device__ __align__(16) float g_xact  [ROWS*DIN];
__device__ __align__(16) float g_Bm    [ROWS*NST];
__device__ __align__(16) float g_Cm    [ROWS*NST];
__device__ __align__(16) float g_dt    [ROWS*NH];
__device__ __align__(16) float g_dlog  [ROWS*NH];
__device__ __align__(16) float g_chunkS[BB*NH*NC*HD*NST];
__device__ __align__(16) float g_lend  [BB*NH*NC];
__device__ __align__(16) float g_SinT  [BB*NH*NC*HD*NST];
__device__ __align__(16) float g_y     [ROWS*DIN];

__device__ __forceinline__ float fsilu(float x) {
    return __fdividef(x, 1.f + __expf(-x));
}

// ================= warp-level bf16 MMA helpers =================
__device__ __forceinline__ void mma16816(float* c, const uint32_t* a, const uint32_t* b) {
    asm volatile(
        "mma.sync.aligned.m16n8k16.row.col.f32.bf16.bf16.f32 "
        "{%0,%1,%2,%3}, {%4,%5,%6,%7}, {%8,%9}, {%0,%1,%2,%3};"
        : "+f"(c[0]), "+f"(c[1]), "+f"(c[2]), "+f"(c[3])
        : "r"(a[0]), "r"(a[1]), "r"(a[2]), "r"(a[3]), "r"(b[0]), "r"(b[1]));
}
__device__ __forceinline__ uint32_t pk(float a, float b) {
    __nv_bfloat162 t = __floats2bfloat162_rn(a, b);
    return *reinterpret_cast<uint32_t*>(&t);
}

#define SSTR 72                       // smem row stride in bf16 elems
#define OFF_AH 0
#define OFF_AL (128*SSTR)
#define OFF_BH (2*128*SSTR)
#define OFF_BL (2*128*SSTR + 64*SSTR)
#define TG_DSMEM ((2*128*SSTR + 2*64*SSTR) * 2)   // 55296 bytes

// ============ tensor-core GEMM: C[4096,Nn] = A[4096,K] @ W[K,Nn], bf16x3 ============
__device__ __forceinline__ void tgemm_body(const float* __restrict__ A,
                                           const float* __restrict__ W,
                                           float* __restrict__ C, int Nn, int K) {
    extern __shared__ __nv_bfloat16 sm[];
    __nv_bfloat16* sAh = sm + OFF_AH;
    __nv_bfloat16* sAl = sm + OFF_AL;
    __nv_bfloat16* sBh = sm + OFF_BH;
    __nv_bfloat16* sBl = sm + OFF_BL;

    const int bm = blockIdx.y * 128;
    const int bn = blockIdx.x * 64;
    const int tid = threadIdx.x;
    const int wid = tid >> 5, lane = tid & 31;
    const int wm = (wid >> 1) * 32;
    const int wn = (wid & 1) * 32;

    float acc[2][4][4];
    #pragma unroll
    for (int i = 0; i < 2; i++)
        #pragma unroll
        for (int j = 0; j < 4; j++)
            #pragma unroll
            for (int k = 0; k < 4; k++) acc[i][j][k] = 0.f;

    for (int k0 = 0; k0 < K; k0 += 64) {
        #pragma unroll
        for (int u = 0; u < 8; ++u) {
            int i = tid + u * 256;
            int r = i >> 4, c4 = (i & 15) << 2;
            float4 v = *(const float4*)(A + (size_t)(bm + r) * K + k0 + c4);
            float h0 = __bfloat162float(__float2bfloat16(v.x));
            float h1 = __bfloat162float(__float2bfloat16(v.y));
            float h2 = __bfloat162float(__float2bfloat16(v.z));
            float h3 = __bfloat162float(__float2bfloat16(v.w));
            int off = r * SSTR + c4;
            *(uint2*)(sAh + off) = make_uint2(pk(h0, h1), pk(h2, h3));
            *(uint2*)(sAl + off) = make_uint2(pk(v.x - h0, v.y - h1), pk(v.z - h2, v.w - h3));
        }
        #pragma unroll
        for (int u = 0; u < 4; ++u) {
            int i = tid + u * 256;
            int n = i & 63, g = i >> 6;
            int col = bn + n;
            float v0 = 0.f, v1 = 0.f, v2 = 0.f, v3 = 0.f;
            if (col < Nn) {
                const float* wp = W + (size_t)(k0 + (g << 2)) * Nn + col;
                v0 = wp[0]; v1 = wp[Nn]; v2 = wp[2 * Nn]; v3 = wp[3 * Nn];
            }
            float h0 = __bfloat162float(__float2bfloat16(v0));
            float h1 = __bfloat162float(__float2bfloat16(v1));
            float h2 = __bfloat162float(__float2bfloat16(v2));
            float h3 = __bfloat162float(__float2bfloat16(v3));
            int off = n * SSTR + (g << 2);
            *(uint2*)(sBh + off) = make_uint2(pk(h0, h1), pk(h2, h3));
            *(uint2*)(sBl + off) = make_uint2(pk(v0 - h0, v1 - h1), pk(v2 - h2, v3 - h3));
        }
        __syncthreads();

        #pragma unroll
        for (int ks = 0; ks < 4; ++ks) {
            const int c = ks * 16 + (lane & 3) * 2;
            const int ra = wm + (lane >> 2);
            uint32_t ah[2][4], al[2][4], bh[4][2], bl[4][2];
            #pragma unroll
            for (int mf = 0; mf < 2; ++mf) {
                int r0 = (ra + mf * 16) * SSTR;
                int r8 = r0 + 8 * SSTR;
                ah[mf][0] = *(const uint32_t*)(sAh + r0 + c);
                ah[mf][1] = *(const uint32_t*)(sAh + r8 + c);
                ah[mf][2] = *(const uint32_t*)(sAh + r0 + c + 8);
                ah[mf][3] = *(const uint32_t*)(sAh + r8 + c + 8);
                al[mf][0] = *(const uint32_t*)(sAl + r0 + c);
                al[mf][1] = *(const uint32_t*)(sAl + r8 + c);
                al[mf][2] = *(const uint32_t*)(sAl + r0 + c + 8);
                al[mf][3] = *(const uint32_t*)(sAl + r8 + c + 8);
            }
            #pragma unroll
            for (int nf = 0; nf < 4; ++nf) {
                int nr = (wn + nf * 8 + (lane >> 2)) * SSTR;
                bh[nf][0] = *(const uint32_t*)(sBh + nr + c);
                bh[nf][1] = *(const uint32_t*)(sBh + nr + c + 8);
                bl[nf][0] = *(const uint32_t*)(sBl + nr + c);
                bl[nf][1] = *(const uint32_t*)(sBl + nr + c + 8);
            }
            #pragma unroll
            for (int mf = 0; mf < 2; ++mf)
                #pragma unroll
                for (int nf = 0; nf < 4; ++nf) {
                    mma16816(acc[mf][nf], ah[mf], bh[nf]);
                    mma16816(acc[mf][nf], ah[mf], bl[nf]);
                    mma16816(acc[mf][nf], al[mf], bh[nf]);
                }
        }
        __syncthreads();
    }

    #pragma unroll
    for (int mf = 0; mf < 2; ++mf) {
        int row0 = bm + wm + mf * 16 + (lane >> 2);
        #pragma unroll
        for (int nf = 0; nf < 4; ++nf) {
            int col = bn + wn + nf * 8 + (lane & 3) * 2;
            if (col < Nn) {
                float* p0 = C + (size_t)row0 * Nn + col;
                float* p1 = C + (size_t)(row0 + 8) * Nn + col;
                p0[0] = acc[mf][nf][0]; p0[1] = acc[mf][nf][1];
                p1[0] = acc[mf][nf][2]; p1[1] = acc[mf][nf][3];
            }
        }
    }
}

__global__ void __launch_bounds__(256) k_tgemm_in(const float* __restrict__ Win) {
    tgemm_body(g_xln, Win, g_zx, NPROJ, DD);
}
__global__ void __launch_bounds__(256) k_tgemm_out(const float* __restrict__ Wout,
                                                   float* __restrict__ out) {
    tgemm_body(g_y, Wout, out, DD, DIN);
}

// ---------------- K1: LayerNorm + residual copy ----------------
__global__ void __launch_bounds__(256) k_ln(const float* __restrict__ hid,
                                            const float* __restrict__ w,
                                            const float* __restrict__ b,
                                            float* __restrict__ resid) {
    int row = blockIdx.x, t = threadIdx.x;
    float v = hid[row*DD + t];
    float s = v, q = v*v;
    #pragma unroll
    for (int o = 16; o; o >>= 1) {
        s += __shfl_xor_sync(0xffffffffu, s, o);
        q += __shfl_xor_sync(0xffffffffu, q, o);
    }
    __shared__ float r1[8], r2[8];
    if ((t & 31) == 0) { r1[t>>5] = s; r2[t>>5] = q; }
    __syncthreads();
    __shared__ float smu, srs;
    if (t == 0) {
        float S = 0.f, Qs = 0.f;
        for (int i = 0; i < 8; i++) { S += r1[i]; Qs += r2[i]; }
        float mu = S / 256.f;
        smu = mu;
        srs = rsqrtf(Qs/256.f - mu*mu + 1e-5f);
    }
    __syncthreads();
    g_xln[row*DD + t] = (v - smu) * srs * w[t] + b[t];
    resid[row*DD + t] = v;
}

// ---------------- K3: causal depthwise conv + SiLU, and softplus(dt) ----------------
__global__ void __launch_bounds__(256) k_conv(const float* __restrict__ cw,
                                              const float* __restrict__ cb,
                                              const float* __restrict__ dtb,
                                              const float* __restrict__ Alog) {
    int idx = blockIdx.x * 256 + threadIdx.x;
    if (idx >= ROWS * 648) return;
    int c = idx % 648;
    int row = idx / 648;
    int b = row / LL, l = row % LL;
    if (c < CDIM) {
        float acc = cb[c];
        #pragma unroll
        for (int k = 0; k < 4; k++) {
            int ls = l + k - 3;
            if (ls >= 0) acc += cw[c*4 + k] * g_zx[(b*LL + ls)*NPROJ + 512 + c];
        }
        float sv = fsilu(acc);
        if (c < DIN)        g_xact[row*DIN + c] = sv;
        else if (c < 576)   g_Bm[row*NST + (c - 512)] = sv;
        else                g_Cm[row*NST + (c - 576)] = sv;
    } else {
        int h = c - CDIM;
        float raw = g_zx[row*NPROJ + 1152 + h] + dtb[h];
        float dt = (raw > 20.f) ? raw : log1pf(__expf(raw));
        g_dt[row*NH + h]   = dt;
        g_dlog[row*NH + h] = -dt * __expf(Alog[h]);
    }
}

// ---- shared helper: inclusive warp-scan of 64 values (threads 0..63) ----
__device__ __forceinline__ void scan64(float* sl, float* sw0tot, int tid, float v) {
    if (tid < 64) {
        #pragma unroll
        for (int o = 1; o < 32; o <<= 1) {
            float n = __shfl_up_sync(0xffffffffu, v, o);
            if ((tid & 31) >= o) v += n;
        }
        sl[tid] = v;
        if (tid == 31) *sw0tot = v;
    }
    __syncthreads();
    if (tid >= 32 && tid < 64) sl[tid] += *sw0tot;
    __syncthreads();
}

// ---------------- K4: per-chunk partial state ----------------
__global__ void __launch_bounds__(256) k_cstate() {
    __shared__ float sx[64][65];
    __shared__ float sb[64][65];
    __shared__ float sl[64], scoef[64], sw0;
    int bid = blockIdx.x;
    int c = bid & 31, h = (bid >> 5) & 7, b = bid >> 8;
    int tid = threadIdx.x;
    int t0 = b*LL + c*QC;

    float lv = (tid < 64) ? g_dlog[(t0 + tid)*NH + h] : 0.f;
    scan64(sl, &sw0, tid, lv);
    float lend = sl[63];
    if (tid < 64) scoef[tid] = __expf(lend - sl[tid]) * g_dt[(t0 + tid)*NH + h];
    #pragma unroll
    for (int u = 0; u < 4; ++u) {
        int i = tid + u*256;                    // 0..1023 float4 slots
        int j = i >> 4, p4 = (i & 15) << 2;
        float4 vx = *(const float4*)(g_xact + (size_t)(t0 + j)*DIN + h*HD + p4);
        float4 vb = *(const float4*)(g_Bm   + (size_t)(t0 + j)*NST + p4);
        sx[j][p4] = vx.x; sx[j][p4+1] = vx.y; sx[j][p4+2] = vx.z; sx[j][p4+3] = vx.w;
        sb[j][p4] = vb.x; sb[j][p4+1] = vb.y; sb[j][p4+2] = vb.z; sb[j][p4+3] = vb.w;
    }
    __syncthreads();
    if (tid == 0) g_lend[bid] = lend;

    int tx = tid & 15, ty = tid >> 4;
    int p0 = ty*4, n0 = tx*4;
    float acc[4][4];
    #pragma unroll
    for (int i = 0; i < 4; i++)
        #pragma unroll
        for (int j = 0; j < 4; j++) acc[i][j] = 0.f;
    for (int j = 0; j < 64; ++j) {
        float cf = scoef[j];
        float a[4], bb[4];
        #pragma unroll
        for (int i = 0; i < 4; i++) { a[i] = cf * sx[j][p0+i]; bb[i] = sb[j][n0+i]; }
        #pragma unroll
        for (int i = 0; i < 4; i++)
            #pragma unroll
            for (int n = 0; n < 4; n++) acc[i][n] += a[i]*bb[n];
    }
    float* op = g_chunkS + (size_t)bid*4096;
    #pragma unroll
    for (int i = 0; i < 4; i++)
        #pragma unroll
        for (int n = 0; n < 4; n++) op[(p0+i)*64 + n0+n] = acc[i][n];
}

// ---------------- K5: inter-chunk recurrence ----------------
__global__ void __launch_bounds__(256) k_seq() {
    int bh = blockIdx.x >> 4, part = blockIdx.x & 15, tid = threadIdx.x;
    int e = part * 256 + tid;
    int tr = (e & 63) * 64 + (e >> 6);
    float s = 0.f;
    for (int c = 0; c < NC; c++) {
        size_t base = (size_t)(bh*NC + c)*4096;
        float a = __expf(g_lend[bh*NC + c]);
        g_SinT[base + tr] = s;
        s = s*a + g_chunkS[base + e];
    }
}

// ---------------- K6: intra-chunk Y + inter-chunk contribution + D*x ----------------
__global__ void __launch_bounds__(256) k_y(const float* __restrict__ Dp) {
    __shared__ float bufA[64*65];
    __shared__ float bufB[64*65];
    __shared__ float sl[64], sdt[64], sw0;
    int bid = blockIdx.x;
    int c = bid & 31, h = (bid >> 5) & 7, b = bid >> 8;
    int tid = threadIdx.x;
    int t0 = b*LL + c*QC;

    #pragma unroll
    for (int u = 0; u < 4; ++u) {
        int i = tid + u*256;
        int r = i >> 4, q4 = (i & 15) << 2;
        float4 vb = *(const float4*)(g_Bm + (size_t)(t0 + r)*NST + q4);
        float4 vc = *(const float4*)(g_Cm + (size_t)(t0 + r)*NST + q4);
        bufA[r*65 + q4] = vb.x; bufA[r*65 + q4+1] = vb.y; bufA[r*65 + q4+2] = vb.z; bufA[r*65 + q4+3] = vb.w;
        bufB[r*65 + q4] = vc.x; bufB[r*65 + q4+1] = vc.y; bufB[r*65 + q4+2] = vc.z; bufB[r*65 + q4+3] = vc.w;
    }
    float lv = (tid < 64) ? g_dlog[(t0 + tid)*NH + h] : 0.f;
    if (tid < 64) sdt[tid] = g_dt[(t0 + tid)*NH + h];
    scan64(sl, &sw0, tid, lv);

    int tx = tid & 15, ty = tid >> 4;
    int ti = ty*4, j0 = tx*4;
    float Lts[4], Ljs[4], dts[4], expL[4];
    #pragma unroll
    for (int i = 0; i < 4; i++) {
        Lts[i] = sl[ti + i];  Ljs[i] = sl[j0 + i];  dts[i] = sdt[j0 + i];
        expL[i] = __expf(Lts[i]);
    }

    float g[4][4];
    #pragma unroll
    for (int i = 0; i < 4; i++)
        #pragma unroll
        for (int j = 0; j < 4; j++) g[i][j] = 0.f;
    for (int n = 0; n < 64; ++n) {
        float cv[4], bv[4];
        #pragma unroll
        for (int i = 0; i < 4; i++) { cv[i] = bufB[(ti+i)*65 + n]; bv[i] = bufA[(j0+i)*65 + n]; }
        #pragma unroll
        for (int i = 0; i < 4; i++)
            #pragma unroll
            for (int j = 0; j < 4; j++) g[i][j] += cv[i]*bv[j];
    }

    const float* sinp = g_SinT + (size_t)bid*4096;
    float Y[4][4];
    #pragma unroll
    for (int i = 0; i < 4; i++)
        #pragma unroll
        for (int j = 0; j < 4; j++) Y[i][j] = 0.f;
    for (int n = 0; n < 64; ++n) {
        float4 sv4 = *(const float4*)(sinp + n*64 + j0);
        float sv[4] = {sv4.x, sv4.y, sv4.z, sv4.w};
        float cvv[4];
        #pragma unroll
        for (int i = 0; i < 4; i++) cvv[i] = expL[i] * bufB[(ti+i)*65 + n];
        #pragma unroll
        for (int i = 0; i < 4; i++)
            #pragma unroll
            for (int j = 0; j < 4; j++) Y[i][j] += cvv[i]*sv[j];
    }
    __syncthreads();

    #pragma unroll
    for (int i = 0; i < 4; i++)
        #pragma unroll
        for (int j = 0; j < 4; j++) {
            int tt = ti + i, jj = j0 + j;
            bufA[tt*65 + jj] = (tt >= jj) ? __expf(Lts[i] - Ljs[j]) * dts[j] * g[i][j] : 0.f;
        }
    #pragma unroll
    for (int u = 0; u < 4; ++u) {
        int i = tid + u*256;
        int r = i >> 4, q4 = (i & 15) << 2;
        float4 vx = *(const float4*)(g_xact + (size_t)(t0 + r)*DIN + h*HD + q4);
        bufB[r*65 + q4] = vx.x; bufB[r*65 + q4+1] = vx.y; bufB[r*65 + q4+2] = vx.z; bufB[r*65 + q4+3] = vx.w;
    }
    __syncthreads();

    for (int j = 0; j < 64; ++j) {
        float mv[4], xv[4];
        #pragma unroll
        for (int i = 0; i < 4; i++) { mv[i] = bufA[(ti+i)*65 + j]; xv[i] = bufB[j*65 + j0 + i]; }
        #pragma unroll
        for (int i = 0; i < 4; i++)
            #pragma unroll
            for (int jj = 0; jj < 4; jj++) Y[i][jj] += mv[i]*xv[jj];
    }

    float Dh = Dp[h];
    #pragma unroll
    for (int i = 0; i < 4; i++)
        #pragma unroll
        for (int j = 0; j < 4; j++) {
            float yv = Y[i][j] + Dh * bufB[(ti+i)*65 + j0 + j];
            g_y[(t0 + ti + i)*DIN + h*HD + j0 + j] = yv;
        }
}

// ---------------- K7: gating + RMSNorm ----------------
__global__ void __launch_bounds__(256) k_gate(const float* __restrict__ rmsw) {
    int row = blockIdx.x, t = threadIdx.x;
    float gv[2]; float ss = 0.f;
    #pragma unroll
    for (int k = 0; k < 2; k++) {
        int i = t + k*256;
        float z = g_zx[row*NPROJ + i];
        float v = g_y[row*DIN + i] * fsilu(z);
        gv[k] = v; ss += v*v;
    }
    #pragma unroll
    for (int o = 16; o; o >>= 1) ss += __shfl_xor_sync(0xffffffffu, ss, o);
    __shared__ float red[8];
    if ((t & 31) == 0) red[t>>5] = ss;
    __syncthreads();
    __shared__ float scale;
    if (t == 0) {
        float tot = 0.f;
        for (int i = 0; i < 8; i++) tot += red[i];
        scale = rsqrtf(tot/512.f + 1e-5f);
    }
    __syncthreads();
    #pragma unroll
    for (int k = 0; k < 2; k++) {
        int i = t + k*256;
        g_y[row*DIN + i] = gv[k] * scale * rmsw[i];
    }
}

// ---------------- launch ----------------
extern "C" void kernel_launch(void* const* d_in, const int* in_sizes, int n_in,
                              void* d_out, int out_size) {
    const float* hid   = (const float*)d_in[0];
    const float* normw = (const float*)d_in[1];
    const float* normb = (const float*)d_in[2];
    const float* Win   = (const float*)d_in[3];
    const float* convw = (const float*)d_in[4];
    const float* convb = (const float*)d_in[5];
    const float* dtb   = (const float*)d_in[6];
    const float* Alog  = (const float*)d_in[7];
    const float* Dp    = (const float*)d_in[8];
    const float* rmsw  = (const float*)d_in[9];
    const float* Wout  = (const float*)d_in[10];
    float* out   = (float*)d_out;
    float* resid = out + out_size/2;

    cudaFuncSetAttribute(k_tgemm_in,  cudaFuncAttributeMaxDynamicSharedMemorySize, TG_DSMEM);
    cudaFuncSetAttribute(k_tgemm_out, cudaFuncAttributeMaxDynamicSharedMemorySize, TG_DSMEM);

    k_ln       <<<ROWS, 256>>>(hid, normw, normb, resid);
    k_tgemm_in <<<dim3((NPROJ + 63)/64, ROWS/128), 256, TG_DSMEM>>>(Win);
    k_conv     <<<(ROWS*648 + 255)/256, 256>>>(convw, convb, dtb, Alog);
    k_cstate   <<<BB*NH*NC, 256>>>();
    k_seq      <<<BB*NH*16, 256>>>();
    k_y        <<<BB*NH*NC, 256>>>(Dp);
    k_gate     <<<ROWS, 256>>>(rmsw);
    k_tgemm_out<<<dim3(DD/64, ROWS/128), 256, TG_DSMEM>>>(Wout, out);
}

// round 5
// speedup vs baseline: 4.0201x; 1.2925x over previous
#include <cuda_runtime.h>
#include <cuda_bf16.h>
#include <math.h>
#include <stdint.h>

// ---------------- problem constants ----------------
#define BB    2
#define LL    2048
#define DD    256
#define DIN   512
#define NH    8
#define HD    64
#define NST   64
#define CDIM  640
#define NPROJ 1160
#define ROWS  (BB*LL)      // 4096
#define NC    32           // chunks per sequence
#define QC    64           // chunk length

// ---------------- scratch (device globals; no runtime alloc) ----------------
__device__ __align__(16) float g_xln   [ROWS*DD];
__device__ __align__(16) float g_zx    [ROWS*NPROJ];
__device__ __align__(16) float g_xact  [ROWS*DIN];
__device__ __align__(16) float g_Bm    [ROWS*NST];
__device__ __align__(16) float g_Cm    [ROWS*NST];
__device__ __align__(16) float g_dt    [ROWS*NH];
__device__ __align__(16) float g_dlog  [ROWS*NH];
__device__ __align__(16) float g_chunkS[BB*NH*NC*HD*NST];   // [p][n]
__device__ __align__(16) float g_lend  [BB*NH*NC];
__device__ __align__(16) float g_Sin   [BB*NH*NC*HD*NST];   // state entering chunk [p][n]
__device__ __align__(16) float g_y     [ROWS*DIN];

__device__ __forceinline__ float fsilu(float x) {
    return __fdividef(x, 1.f + __expf(-x));
}

// ================= warp-level bf16 MMA helpers =================
__device__ __forceinline__ void mma16816(float* c, const uint32_t* a, const uint32_t* b) {
    asm volatile(
        "mma.sync.aligned.m16n8k16.row.col.f32.bf16.bf16.f32 "
        "{%0,%1,%2,%3}, {%4,%5,%6,%7}, {%8,%9}, {%0,%1,%2,%3};"
        : "+f"(c[0]), "+f"(c[1]), "+f"(c[2]), "+f"(c[3])
        : "r"(a[0]), "r"(a[1]), "r"(a[2]), "r"(a[3]), "r"(b[0]), "r"(b[1]));
}
__device__ __forceinline__ uint32_t pk(float a, float b) {
    __nv_bfloat162 t = __floats2bfloat162_rn(a, b);
    return *reinterpret_cast<uint32_t*>(&t);
}
// row-major hi/lo store of 4 consecutive elements at [r][q4], stride 72
__device__ __forceinline__ void store4R(__nv_bfloat16* sh, __nv_bfloat16* slo,
                                        int r, int q4, float4 v) {
    float h0 = __bfloat162float(__float2bfloat16(v.x));
    float h1 = __bfloat162float(__float2bfloat16(v.y));
    float h2 = __bfloat162float(__float2bfloat16(v.z));
    float h3 = __bfloat162float(__float2bfloat16(v.w));
    int off = r * 72 + q4;
    *(uint2*)(sh  + off) = make_uint2(pk(h0, h1), pk(h2, h3));
    *(uint2*)(slo + off) = make_uint2(pk(v.x - h0, v.y - h1), pk(v.z - h2, v.w - h3));
}
// transposed hi/lo store: element k of v goes to [q4+k][j], stride 72
__device__ __forceinline__ void store4T(__nv_bfloat16* sh, __nv_bfloat16* slo,
                                        int q4, int j, float4 v) {
    float f[4] = {v.x, v.y, v.z, v.w};
    #pragma unroll
    for (int k = 0; k < 4; k++) {
        float hi = __bfloat162float(__float2bfloat16(f[k]));
        sh [(q4 + k) * 72 + j] = __float2bfloat16(hi);
        slo[(q4 + k) * 72 + j] = __float2bfloat16(f[k] - hi);
    }
}
// load A-frag (m16 rows r0/r0+8, k cols c/c+8) from stride-72 bf16 tile
__device__ __forceinline__ void lda(uint32_t* a, const __nv_bfloat16* s, int r0, int c) {
    int o0 = r0 * 72 + c, o8 = o0 + 8 * 72;
    a[0] = *(const uint32_t*)(s + o0);
    a[1] = *(const uint32_t*)(s + o8);
    a[2] = *(const uint32_t*)(s + o0 + 8);
    a[3] = *(const uint32_t*)(s + o8 + 8);
}
__device__ __forceinline__ void ldb(uint32_t* b, const __nv_bfloat16* s, int n, int c) {
    int o = n * 72 + c;
    b[0] = *(const uint32_t*)(s + o);
    b[1] = *(const uint32_t*)(s + o + 8);
}

#define SSTR 72
#define OFF_AH 0
#define OFF_AL (128*SSTR)
#define OFF_BH (2*128*SSTR)
#define OFF_BL (2*128*SSTR + 64*SSTR)
#define TG_DSMEM ((2*128*SSTR + 2*64*SSTR) * 2)   // 55296 bytes

// ============ tensor-core GEMM: C[4096,Nn] = A[4096,K] @ W[K,Nn], bf16x3 ============
__device__ __forceinline__ void tgemm_body(const float* __restrict__ A,
                                           const float* __restrict__ W,
                                           float* __restrict__ C, int Nn, int K) {
    extern __shared__ __nv_bfloat16 sm[];
    __nv_bfloat16* sAh = sm + OFF_AH;
    __nv_bfloat16* sAl = sm + OFF_AL;
    __nv_bfloat16* sBh = sm + OFF_BH;
    __nv_bfloat16* sBl = sm + OFF_BL;

    const int bm = blockIdx.y * 128;
    const int bn = blockIdx.x * 64;
    const int tid = threadIdx.x;
    const int wid = tid >> 5, lane = tid & 31;
    const int wm = (wid >> 1) * 32;
    const int wn = (wid & 1) * 32;

    float acc[2][4][4];
    #pragma unroll
    for (int i = 0; i < 2; i++)
        #pragma unroll
        for (int j = 0; j < 4; j++)
            #pragma unroll
            for (int k = 0; k < 4; k++) acc[i][j][k] = 0.f;

    for (int k0 = 0; k0 < K; k0 += 64) {
        #pragma unroll
        for (int u = 0; u < 8; ++u) {
            int i = tid + u * 256;
            int r = i >> 4, c4 = (i & 15) << 2;
            float4 v = *(const float4*)(A + (size_t)(bm + r) * K + k0 + c4);
            store4R(sAh, sAl, r, c4, v);
        }
        #pragma unroll
        for (int u = 0; u < 4; ++u) {
            int i = tid + u * 256;
            int n = i & 63, g = i >> 6;
            int col = bn + n;
            float4 v = make_float4(0.f, 0.f, 0.f, 0.f);
            if (col < Nn) {
                const float* wp = W + (size_t)(k0 + (g << 2)) * Nn + col;
                v = make_float4(wp[0], wp[Nn], wp[2 * Nn], wp[3 * Nn]);
            }
            store4R(sBh, sBl, n, g << 2, v);
        }
        __syncthreads();

        #pragma unroll
        for (int ks = 0; ks < 4; ++ks) {
            const int c = ks * 16 + (lane & 3) * 2;
            const int ra = wm + (lane >> 2);
            uint32_t ah[2][4], al[2][4], bh[4][2], bl[4][2];
            #pragma unroll
            for (int mf = 0; mf < 2; ++mf) {
                lda(ah[mf], sAh, ra + mf * 16, c);
                lda(al[mf], sAl, ra + mf * 16, c);
            }
            #pragma unroll
            for (int nf = 0; nf < 4; ++nf) {
                ldb(bh[nf], sBh, wn + nf * 8 + (lane >> 2), c);
                ldb(bl[nf], sBl, wn + nf * 8 + (lane >> 2), c);
            }
            #pragma unroll
            for (int mf = 0; mf < 2; ++mf)
                #pragma unroll
                for (int nf = 0; nf < 4; ++nf) {
                    mma16816(acc[mf][nf], ah[mf], bh[nf]);
                    mma16816(acc[mf][nf], ah[mf], bl[nf]);
                    mma16816(acc[mf][nf], al[mf], bh[nf]);
                }
        }
        __syncthreads();
    }

    #pragma unroll
    for (int mf = 0; mf < 2; ++mf) {
        int row0 = bm + wm + mf * 16 + (lane >> 2);
        #pragma unroll
        for (int nf = 0; nf < 4; ++nf) {
            int col = bn + wn + nf * 8 + (lane & 3) * 2;
            if (col < Nn) {
                float* p0 = C + (size_t)row0 * Nn + col;
                float* p1 = C + (size_t)(row0 + 8) * Nn + col;
                p0[0] = acc[mf][nf][0]; p0[1] = acc[mf][nf][1];
                p1[0] = acc[mf][nf][2]; p1[1] = acc[mf][nf][3];
            }
        }
    }
}

__global__ void __launch_bounds__(256) k_tgemm_in(const float* __restrict__ Win) {
    tgemm_body(g_xln, Win, g_zx, NPROJ, DD);
}
__global__ void __launch_bounds__(256) k_tgemm_out(const float* __restrict__ Wout,
                                                   float* __restrict__ out) {
    tgemm_body(g_y, Wout, out, DD, DIN);
}

// ---------------- K1: LayerNorm + residual copy ----------------
__global__ void __launch_bounds__(256) k_ln(const float* __restrict__ hid,
                                            const float* __restrict__ w,
                                            const float* __restrict__ b,
                                            float* __restrict__ resid) {
    int row = blockIdx.x, t = threadIdx.x;
    float v = hid[row*DD + t];
    float s = v, q = v*v;
    #pragma unroll
    for (int o = 16; o; o >>= 1) {
        s += __shfl_xor_sync(0xffffffffu, s, o);
        q += __shfl_xor_sync(0xffffffffu, q, o);
    }
    __shared__ float r1[8], r2[8];
    if ((t & 31) == 0) { r1[t>>5] = s; r2[t>>5] = q; }
    __syncthreads();
    __shared__ float smu, srs;
    if (t == 0) {
        float S = 0.f, Qs = 0.f;
        for (int i = 0; i < 8; i++) { S += r1[i]; Qs += r2[i]; }
        float mu = S / 256.f;
        smu = mu;
        srs = rsqrtf(Qs/256.f - mu*mu + 1e-5f);
    }
    __syncthreads();
    g_xln[row*DD + t] = (v - smu) * srs * w[t] + b[t];
    resid[row*DD + t] = v;
}

// ---------------- K3: causal depthwise conv + SiLU, and softplus(dt) ----------------
__global__ void __launch_bounds__(256) k_conv(const float* __restrict__ cw,
                                              const float* __restrict__ cb,
                                              const float* __restrict__ dtb,
                                              const float* __restrict__ Alog) {
    int idx = blockIdx.x * 256 + threadIdx.x;
    if (idx >= ROWS * 648) return;
    int c = idx % 648;
    int row = idx / 648;
    int b = row / LL, l = row % LL;
    if (c < CDIM) {
        float acc = cb[c];
        #pragma unroll
        for (int k = 0; k < 4; k++) {
            int ls = l + k - 3;
            if (ls >= 0) acc += cw[c*4 + k] * g_zx[(b*LL + ls)*NPROJ + 512 + c];
        }
        float sv = fsilu(acc);
        if (c < DIN)        g_xact[row*DIN + c] = sv;
        else if (c < 576)   g_Bm[row*NST + (c - 512)] = sv;
        else                g_Cm[row*NST + (c - 576)] = sv;
    } else {
        int h = c - CDIM;
        float raw = g_zx[row*NPROJ + 1152 + h] + dtb[h];
        float dt = (raw > 20.f) ? raw : log1pf(__expf(raw));
        g_dt[row*NH + h]   = dt;
        g_dlog[row*NH + h] = -dt * __expf(Alog[h]);
    }
}

// ---- inclusive warp-scan of 64 values (threads 0..63) ----
__device__ __forceinline__ void scan64(float* sl, float* sw0tot, int tid, float v) {
    if (tid < 64) {
        #pragma unroll
        for (int o = 1; o < 32; o <<= 1) {
            float n = __shfl_up_sync(0xffffffffu, v, o);
            if ((tid & 31) >= o) v += n;
        }
        sl[tid] = v;
        if (tid == 31) *sw0tot = v;
    }
    __syncthreads();
    if (tid >= 32 && tid < 64) sl[tid] += *sw0tot;
    __syncthreads();
}

// ---------------- K4: per-chunk partial state via HMMA bf16x3 ----------------
// S[p][n] = sum_j (coef_j * x_j[p]) * Bm_j[n]
__global__ void __launch_bounds__(256) k_cstate() {
    __shared__ __nv_bfloat16 sXh[64*72], sXl[64*72], sBTh[64*72], sBTl[64*72];
    __shared__ float sl[64], scoef[64], sw0;
    int bid = blockIdx.x;
    int c = bid & 31, h = (bid >> 5) & 7, b = bid >> 8;
    int tid = threadIdx.x;
    int t0 = b*LL + c*QC;

    float lv = (tid < 64) ? g_dlog[(t0 + tid)*NH + h] : 0.f;
    scan64(sl, &sw0, tid, lv);
    float lend = sl[63];
    if (tid < 64) scoef[tid] = __expf(lend - sl[tid]) * g_dt[(t0 + tid)*NH + h];
    if (tid == 0) g_lend[bid] = lend;
    __syncthreads();

    // stage XwT[p][j] = coef_j*x_j[p] and BmT[n][j] = Bm_j[n], both hi/lo
    #pragma unroll
    for (int u = 0; u < 4; ++u) {
        int i = tid + u * 256;                 // 0..1023
        int j = i >> 4, q4 = (i & 15) << 2;
        float cf = scoef[j];
        float4 vx = *(const float4*)(g_xact + (size_t)(t0 + j)*DIN + h*HD + q4);
        vx.x *= cf; vx.y *= cf; vx.z *= cf; vx.w *= cf;
        float4 vb = *(const float4*)(g_Bm + (size_t)(t0 + j)*NST + q4);
        store4T(sXh,  sXl,  q4, j, vx);
        store4T(sBTh, sBTl, q4, j, vb);
    }
    __syncthreads();

    const int wid = tid >> 5, lane = tid & 31;
    const int wm = (wid >> 1) * 16, wn = (wid & 1) * 32;
    const int r0 = wm + (lane >> 2);
    float acc[4][4];
    #pragma unroll
    for (int i = 0; i < 4; i++)
        #pragma unroll
        for (int j = 0; j < 4; j++) acc[i][j] = 0.f;

    #pragma unroll
    for (int ks = 0; ks < 4; ++ks) {
        const int cc = ks * 16 + (lane & 3) * 2;
        uint32_t ah[4], al[4], bh[4][2], bl[4][2];
        lda(ah, sXh, r0, cc);
        lda(al, sXl, r0, cc);
        #pragma unroll
        for (int nf = 0; nf < 4; ++nf) {
            ldb(bh[nf], sBTh, wn + nf * 8 + (lane >> 2), cc);
            ldb(bl[nf], sBTl, wn + nf * 8 + (lane >> 2), cc);
        }
        #pragma unroll
        for (int nf = 0; nf < 4; ++nf) {
            mma16816(acc[nf], ah, bh[nf]);
            mma16816(acc[nf], ah, bl[nf]);
            mma16816(acc[nf], al, bh[nf]);
        }
    }

    float* op = g_chunkS + (size_t)bid * 4096;
    #pragma unroll
    for (int nf = 0; nf < 4; ++nf) {
        int n0 = wn + nf * 8 + (lane & 3) * 2;
        op[r0*64 + n0]     = acc[nf][0]; op[r0*64 + n0 + 1]     = acc[nf][1];
        op[(r0+8)*64 + n0] = acc[nf][2]; op[(r0+8)*64 + n0 + 1] = acc[nf][3];
    }
}

// ---------------- K5: inter-chunk recurrence (float4, no transpose) ----------------
__global__ void __launch_bounds__(256) k_seq() {
    int bh = blockIdx.x >> 2, part = blockIdx.x & 3, tid = threadIdx.x;
    int e = (part * 256 + tid) * 4;
    float4 s = make_float4(0.f, 0.f, 0.f, 0.f);
    for (int c = 0; c < NC; c++) {
        size_t base = (size_t)(bh*NC + c)*4096;
        float a = __expf(g_lend[bh*NC + c]);
        *(float4*)(g_Sin + base + e) = s;
        float4 v = *(const float4*)(g_chunkS + base + e);
        s.x = s.x*a + v.x; s.y = s.y*a + v.y;
        s.z = s.z*a + v.z; s.w = s.w*a + v.w;
    }
}

// ---------------- K6: intra-chunk Y via HMMA bf16x3 ----------------
// G = C @ B^T (masked/scaled -> M);  Y = M @ X^T + expL_t * (C @ Sin^T) + D*x
__global__ void __launch_bounds__(256) k_y(const float* __restrict__ Dp) {
    extern __shared__ __nv_bfloat16 sy[];
    __nv_bfloat16* sBh = sy;              // later reused for M (hi)
    __nv_bfloat16* sBl = sy + 4608;       // later reused for M (lo)
    __nv_bfloat16* sCh = sy + 2*4608;
    __nv_bfloat16* sCl = sy + 3*4608;
    __nv_bfloat16* sSh = sy + 4*4608;
    __nv_bfloat16* sSl = sy + 5*4608;
    __nv_bfloat16* sXh = sy + 6*4608;     // X transposed [p][j]
    __nv_bfloat16* sXl = sy + 7*4608;
    __shared__ float sl[64], sdt[64], sw0;

    int bid = blockIdx.x;
    int c = bid & 31, h = (bid >> 5) & 7, b = bid >> 8;
    int tid = threadIdx.x;
    int t0 = b*LL + c*QC;

    float lv = (tid < 64) ? g_dlog[(t0 + tid)*NH + h] : 0.f;
    if (tid < 64) sdt[tid] = g_dt[(t0 + tid)*NH + h];
    scan64(sl, &sw0, tid, lv);

    #pragma unroll
    for (int u = 0; u < 4; ++u) {
        int i = tid + u * 256;                 // 0..1023
        int r = i >> 4, q4 = (i & 15) << 2;
        float4 vb = *(const float4*)(g_Bm + (size_t)(t0 + r)*NST + q4);
        float4 vc = *(const float4*)(g_Cm + (size_t)(t0 + r)*NST + q4);
        float4 vs = *(const float4*)(g_Sin + (size_t)bid*4096 + r*64 + q4);  // [p=r][n=q4]
        float4 vx = *(const float4*)(g_xact + (size_t)(t0 + r)*DIN + h*HD + q4);
        store4R(sBh, sBl, r, q4, vb);
        store4R(sCh, sCl, r, q4, vc);
        store4R(sSh, sSl, r, q4, vs);
        store4T(sXh, sXl, q4, r, vx);          // XT[p][j=r]
    }
    __syncthreads();

    const int wid = tid >> 5, lane = tid & 31;
    const int wm = (wid >> 1) * 16, wn = (wid & 1) * 32;
    const int r0 = wm + (lane >> 2);

    float g[4][4], g3[4][4];
    #pragma unroll
    for (int i = 0; i < 4; i++)
        #pragma unroll
        for (int j = 0; j < 4; j++) { g[i][j] = 0.f; g3[i][j] = 0.f; }

    #pragma unroll
    for (int ks = 0; ks < 4; ++ks) {
        const int cc = ks * 16 + (lane & 3) * 2;
        uint32_t ah[4], al[4], bh[2], bl[2];
        lda(ah, sCh, r0, cc);
        lda(al, sCl, r0, cc);
        #pragma unroll
        for (int nf = 0; nf < 4; ++nf) {
            int nr = wn + nf * 8 + (lane >> 2);
            ldb(bh, sBh, nr, cc);  ldb(bl, sBl, nr, cc);
            mma16816(g[nf], ah, bh);
            mma16816(g[nf], ah, bl);
            mma16816(g[nf], al, bh);
            ldb(bh, sSh, nr, cc);  ldb(bl, sSl, nr, cc);
            mma16816(g3[nf], ah, bh);
            mma16816(g3[nf], ah, bl);
            mma16816(g3[nf], al, bh);
        }
    }
    __syncthreads();   // everyone done reading B -> reuse as M

    // M[t][j] = (t>=j) ? exp(L_t - L_j) * dt_j * G[t][j] : 0   (bf16 hi/lo)
    float Lr0 = sl[r0], Lr8 = sl[r0 + 8];
    #pragma unroll
    for (int nf = 0; nf < 4; ++nf) {
        int jn = wn + nf * 8 + (lane & 3) * 2;
        #pragma unroll
        for (int jj = 0; jj < 2; ++jj) {
            int j = jn + jj;
            float Lj = sl[j], dtj = sdt[j];
            float m0 = (r0     >= j) ? __expf(Lr0 - Lj) * dtj * g[nf][jj]     : 0.f;
            float m8 = (r0 + 8 >= j) ? __expf(Lr8 - Lj) * dtj * g[nf][2 + jj] : 0.f;
            float h0 = __bfloat162float(__float2bfloat16(m0));
            float h8 = __bfloat162float(__float2bfloat16(m8));
            sBh[r0*72 + j]     = __float2bfloat16(h0);
            sBl[r0*72 + j]     = __float2bfloat16(m0 - h0);
            sBh[(r0+8)*72 + j] = __float2bfloat16(h8);
            sBl[(r0+8)*72 + j] = __float2bfloat16(m8 - h8);
        }
    }
    __syncthreads();

    // Y = M @ X^T
    float Y[4][4];
    #pragma unroll
    for (int i = 0; i < 4; i++)
        #pragma unroll
        for (int j = 0; j < 4; j++) Y[i][j] = 0.f;
    #pragma unroll
    for (int ks = 0; ks < 4; ++ks) {
        const int cc = ks * 16 + (lane & 3) * 2;
        uint32_t ah[4], al[4], bh[2], bl[2];
        lda(ah, sBh, r0, cc);
        lda(al, sBl, r0, cc);
        #pragma unroll
        for (int nf = 0; nf < 4; ++nf) {
            int nr = wn + nf * 8 + (lane >> 2);
            ldb(bh, sXh, nr, cc);  ldb(bl, sXl, nr, cc);
            mma16816(Y[nf], ah, bh);
            mma16816(Y[nf], ah, bl);
            mma16816(Y[nf], al, bh);
        }
    }

    float e0 = __expf(Lr0), e8 = __expf(Lr8);
    float Dh = Dp[h];
    #pragma unroll
    for (int nf = 0; nf < 4; ++nf) {
        int p0 = wn + nf * 8 + (lane & 3) * 2;
        #pragma unroll
        for (int jj = 0; jj < 2; ++jj) {
            int p = p0 + jj;
            float x0 = __bfloat162float(sXh[p*72 + r0])     + __bfloat162float(sXl[p*72 + r0]);
            float x8 = __bfloat162float(sXh[p*72 + r0 + 8]) + __bfloat162float(sXl[p*72 + r0 + 8]);
            float y0 = Y[nf][jj]     + e0 * g3[nf][jj]     + Dh * x0;
            float y8 = Y[nf][2 + jj] + e8 * g3[nf][2 + jj] + Dh * x8;
            g_y[(size_t)(t0 + r0)*DIN     + h*HD + p] = y0;
            g_y[(size_t)(t0 + r0 + 8)*DIN + h*HD + p] = y8;
        }
    }
}
#define KY_DSMEM (8*4608*2)   // 73728 bytes

// ---------------- K7: gating + RMSNorm ----------------
__global__ void __launch_bounds__(256) k_gate(const float* __restrict__ rmsw) {
    int row = blockIdx.x, t = threadIdx.x;
    float gv[2]; float ss = 0.f;
    #pragma unroll
    for (int k = 0; k < 2; k++) {
        int i = t + k*256;
        float z = g_zx[row*NPROJ + i];
        float v = g_y[row*DIN + i] * fsilu(z);
        gv[k] = v; ss += v*v;
    }
    #pragma unroll
    for (int o = 16; o; o >>= 1) ss += __shfl_xor_sync(0xffffffffu, ss, o);
    __shared__ float red[8];
    if ((t & 31) == 0) red[t>>5] = ss;
    __syncthreads();
    __shared__ float scale;
    if (t == 0) {
        float tot = 0.f;
        for (int i = 0; i < 8; i++) tot += red[i];
        scale = rsqrtf(tot/512.f + 1e-5f);
    }
    __syncthreads();
    #pragma unroll
    for (int k = 0; k < 2; k++) {
        int i = t + k*256;
        g_y[row*DIN + i] = gv[k] * scale * rmsw[i];
    }
}

// ---------------- launch ----------------
extern "C" void kernel_launch(void* const* d_in, const int* in_sizes, int n_in,
                              void* d_out, int out_size) {
    const float* hid   = (const float*)d_in[0];
    const float* normw = (const float*)d_in[1];
    const float* normb = (const float*)d_in[2];
    const float* Win   = (const float*)d_in[3];
    const float* convw = (const float*)d_in[4];
    const float* convb = (const float*)d_in[5];
    const float* dtb   = (const float*)d_in[6];
    const float* Alog  = (const float*)d_in[7];
    const float* Dp    = (const float*)d_in[8];
    const float* rmsw  = (const float*)d_in[9];
    const float* Wout  = (const float*)d_in[10];
    float* out   = (float*)d_out;
    float* resid = out + out_size/2;

    cudaFuncSetAttribute(k_tgemm_in,  cudaFuncAttributeMaxDynamicSharedMemorySize, TG_DSMEM);
    cudaFuncSetAttribute(k_tgemm_out, cudaFuncAttributeMaxDynamicSharedMemorySize, TG_DSMEM);
    cudaFuncSetAttribute(k_y,         cudaFuncAttributeMaxDynamicSharedMemorySize, KY_DSMEM);

    k_ln       <<<ROWS, 256>>>(hid, normw, normb, resid);
    k_tgemm_in <<<dim3((NPROJ + 63)/64, ROWS/128), 256, TG_DSMEM>>>(Win);
    k_conv     <<<(ROWS*648 + 255)/256, 256>>>(convw, convb, dtb, Alog);
    k_cstate   <<<BB*NH*NC, 256>>>();
    k_seq      <<<BB*NH*4, 256>>>();
    k_y        <<<BB*NH*NC, 256, KY_DSMEM>>>(Dp);
    k_gate     <<<ROWS, 256>>>(rmsw);
    k_tgemm_out<<<dim3(DD/64, ROWS/128), 256, TG_DSMEM>>>(Wout, out);
}